// round 5
// baseline (speedup 1.0000x reference)
#include <cuda_runtime.h>
#include <cstdint>

// UpsampleInterp: [1, 80, 96, 112, 16] f32 -> [1, 160, 192, 224, 16] f32
//
// R5: bulk-store writeback. Block = input row (z,y). Threads compute the four
// output rows (2z+dz, 2y+dy) into SMEM with gmem-identical layout, then one
// elected thread issues 4x cp.async.bulk (S2G TMA) of 14336 B each — fully
// sequential DRAM write bursts instead of interleaved STG wavefronts.
// Output-indexed threads: xo = tid>>2 (+112 second half), so STS.128 is
// lane-contiguous / conflict-free. Loads (16/thread) all hit L1/L2.

#define DD 80
#define HH 96
#define WW 112
#define WO (2 * WW)                 // 224
#define HO (2 * HH)                 // 192
#define ROW_F4 (WO * 4)             // 896 float4 per output row
#define ROW_BYTES (ROW_F4 * 16)     // 14336 B
#define SMEM_BYTES (4 * ROW_BYTES)  // 57344 B
#define BLOCK 448

__device__ __forceinline__ float4 f4_avg2(float4 a, float4 b) {
    return make_float4(0.5f * (a.x + b.x), 0.5f * (a.y + b.y),
                       0.5f * (a.z + b.z), 0.5f * (a.w + b.w));
}
__device__ __forceinline__ float4 f4_avg4(float4 a, float4 b, float4 c, float4 d) {
    return make_float4(0.25f * (a.x + b.x + c.x + d.x),
                       0.25f * (a.y + b.y + c.y + d.y),
                       0.25f * (a.z + b.z + c.z + d.z),
                       0.25f * (a.w + b.w + c.w + d.w));
}

__global__ void __launch_bounds__(BLOCK, 3)
upsample_2x_bulk_kernel(const float4* __restrict__ in, float4* __restrict__ out) {
    extern __shared__ float4 sbuf[];  // [4][ROW_F4], rows r = dz*2+dy

    const int c4  = threadIdx.x & 3;
    const int xo0 = threadIdx.x >> 2;       // 0..111
    const int y   = blockIdx.y;
    const int z   = blockIdx.z;
    const int yp  = min(y + 1, HH - 1);
    const int zp  = min(z + 1, DD - 1);

    #define IIDX(zz, yy, xx) ((((zz) * HH + (yy)) * WW + (xx)) * 4 + c4)

    #pragma unroll
    for (int h = 0; h < 2; h++) {
        const int xo = xo0 + h * 112;       // output x position 0..223
        const int x  = xo >> 1;
        const int x1 = min(x + (xo & 1), WW - 1);

        // corners at x (A) and x1 (B); for even xo, B == A (avg2(a,a)=a exact)
        float4 a00 = in[IIDX(z,  y,  x )];
        float4 b00 = in[IIDX(z,  y,  x1)];
        float4 a01 = in[IIDX(z,  yp, x )];
        float4 b01 = in[IIDX(z,  yp, x1)];
        float4 a10 = in[IIDX(zp, y,  x )];
        float4 b10 = in[IIDX(zp, y,  x1)];
        float4 a11 = in[IIDX(zp, yp, x )];
        float4 b11 = in[IIDX(zp, yp, x1)];

        // x-blend
        float4 u00 = f4_avg2(a00, b00);
        float4 u01 = f4_avg2(a01, b01);
        float4 u10 = f4_avg2(a10, b10);
        float4 u11 = f4_avg2(a11, b11);

        const int s = xo * 4 + c4;
        sbuf[0 * ROW_F4 + s] = u00;                       // (dz=0, dy=0)
        sbuf[1 * ROW_F4 + s] = f4_avg2(u00, u01);         // (dz=0, dy=1)
        sbuf[2 * ROW_F4 + s] = f4_avg2(u00, u10);         // (dz=1, dy=0)
        sbuf[3 * ROW_F4 + s] = f4_avg4(u00, u01, u10, u11); // (dz=1, dy=1)
    }
    #undef IIDX

    __syncthreads();

    if (threadIdx.x == 0) {
        asm volatile("fence.proxy.async.shared::cta;" ::: "memory");
        const int zo = 2 * z, yo = 2 * y;
        #pragma unroll
        for (int r = 0; r < 4; r++) {
            const int dz = r >> 1, dy = r & 1;
            float4* dst = out + ((size_t)((zo + dz) * HO + (yo + dy))) * ROW_F4;
            uint32_t src = (uint32_t)__cvta_generic_to_shared(&sbuf[r * ROW_F4]);
            asm volatile(
                "cp.async.bulk.global.shared::cta.bulk_group [%0], [%1], %2;"
                :: "l"(dst), "r"(src), "n"(ROW_BYTES) : "memory");
        }
        asm volatile("cp.async.bulk.commit_group;" ::: "memory");
        asm volatile("cp.async.bulk.wait_group 0;" ::: "memory");
    }
}

extern "C" void kernel_launch(void* const* d_in, const int* in_sizes, int n_in,
                              void* d_out, int out_size) {
    const float4* in  = (const float4*)d_in[0];
    float4*       out = (float4*)d_out;

    cudaFuncSetAttribute(upsample_2x_bulk_kernel,
                         cudaFuncAttributeMaxDynamicSharedMemorySize, SMEM_BYTES);

    dim3 grid(1, HH, DD);  // 7680 blocks, one per input (z,y) row
    upsample_2x_bulk_kernel<<<grid, BLOCK, SMEM_BYTES>>>(in, out);
}

// round 6
// speedup vs baseline: 1.0875x; 1.0875x over previous
#include <cuda_runtime.h>

// UpsampleInterp: [1, 80, 96, 112, 16] f32 -> [1, 160, 192, 224, 16] f32
//
// R6: 256-bit stores. Thread = (input voxel, x-parity px, channel-half c8).
// Each thread loads the 8 clamped corners as v8 (32 B) pairs, blends the x
// pair immediately (px=0 duplicates: avg(a,a)=a exact), and writes its 4
// output voxels' channel-half with st.global.cs.v8.f32 (STG.E.256).
// Lane layout (x_lo, px, c8) -> every warp store is a dense contiguous
// 1024 B range. Doubles write payload per LSU queue slot vs STG.128.

#define DD 80
#define HH 96
#define WW 112
#define HO (2 * HH)
#define WO (2 * WW)
#define TOTAL (DD * HH * WW * 4)   // (voxel, px, c8) items = 3,440,640
#define BLOCK 256

__device__ __forceinline__ void ld_v8(const float* __restrict__ p, float r[8]) {
    asm volatile("ld.global.nc.v8.f32 {%0,%1,%2,%3,%4,%5,%6,%7}, [%8];"
                 : "=f"(r[0]), "=f"(r[1]), "=f"(r[2]), "=f"(r[3]),
                   "=f"(r[4]), "=f"(r[5]), "=f"(r[6]), "=f"(r[7])
                 : "l"(p));
}
__device__ __forceinline__ void st_v8_cs(float* __restrict__ p, const float r[8]) {
    asm volatile("st.global.cs.v8.f32 [%0], {%1,%2,%3,%4,%5,%6,%7,%8};"
                 :: "l"(p),
                    "f"(r[0]), "f"(r[1]), "f"(r[2]), "f"(r[3]),
                    "f"(r[4]), "f"(r[5]), "f"(r[6]), "f"(r[7])
                 : "memory");
}

__global__ void __launch_bounds__(BLOCK)
upsample_2x_v8_kernel(const float* __restrict__ in, float* __restrict__ out) {
    int tid = blockIdx.x * BLOCK + threadIdx.x;

    const int c8 = tid & 1;         // channel half: 8 floats = 32 B
    const int px = (tid >> 1) & 1;  // output x parity
    int t  = tid >> 2;
    const int x  = t % WW;
    int t2 = t / WW;
    const int y  = t2 % HH;
    const int z  = t2 / HH;

    const int x1 = px ? min(x + 1, WW - 1) : x;
    const int yp = min(y + 1, HH - 1);
    const int zp = min(z + 1, DD - 1);

    #define IADDR(zz, yy, xx) (in + ((size_t)(((zz) * HH + (yy)) * WW + (xx)) * 16 + c8 * 8))

    float u00[8], u01[8], u10[8], u11[8], tb[8];

    // x-blend each (z,y) corner pair on load; px=0 -> exact identity
    ld_v8(IADDR(z,  y,  x ), u00);
    ld_v8(IADDR(z,  y,  x1), tb);
    #pragma unroll
    for (int i = 0; i < 8; i++) u00[i] = 0.5f * (u00[i] + tb[i]);

    ld_v8(IADDR(z,  yp, x ), u01);
    ld_v8(IADDR(z,  yp, x1), tb);
    #pragma unroll
    for (int i = 0; i < 8; i++) u01[i] = 0.5f * (u01[i] + tb[i]);

    ld_v8(IADDR(zp, y,  x ), u10);
    ld_v8(IADDR(zp, y,  x1), tb);
    #pragma unroll
    for (int i = 0; i < 8; i++) u10[i] = 0.5f * (u10[i] + tb[i]);

    ld_v8(IADDR(zp, yp, x ), u11);
    ld_v8(IADDR(zp, yp, x1), tb);
    #pragma unroll
    for (int i = 0; i < 8; i++) u11[i] = 0.5f * (u11[i] + tb[i]);
    #undef IADDR

    const int zo = 2 * z, yo = 2 * y, xo = 2 * x + px;
    #define OADDR(zz, yy) (out + ((size_t)(((zz) * HO + (yy)) * WO + xo) * 16 + c8 * 8))

    // (dz=0, dy=0): u00
    st_v8_cs(OADDR(zo, yo), u00);

    // (dz=0, dy=1): avg(u00, u01)
    #pragma unroll
    for (int i = 0; i < 8; i++) tb[i] = 0.5f * (u00[i] + u01[i]);
    st_v8_cs(OADDR(zo, yo + 1), tb);

    // (dz=1, dy=0): avg(u00, u10)
    #pragma unroll
    for (int i = 0; i < 8; i++) tb[i] = 0.5f * (u00[i] + u10[i]);
    st_v8_cs(OADDR(zo + 1, yo), tb);

    // (dz=1, dy=1): avg4
    #pragma unroll
    for (int i = 0; i < 8; i++)
        tb[i] = 0.25f * (u00[i] + u01[i] + u10[i] + u11[i]);
    st_v8_cs(OADDR(zo + 1, yo + 1), tb);
    #undef OADDR
}

extern "C" void kernel_launch(void* const* d_in, const int* in_sizes, int n_in,
                              void* d_out, int out_size) {
    const float* in  = (const float*)d_in[0];
    float*       out = (float*)d_out;

    const int grid = TOTAL / BLOCK;  // 13,440 exactly
    upsample_2x_v8_kernel<<<grid, BLOCK>>>(in, out);
}

// round 7
// speedup vs baseline: 1.1066x; 1.0176x over previous
#include <cuda_runtime.h>

// UpsampleInterp: [1, 80, 96, 112, 16] f32 -> [1, 160, 192, 224, 16] f32
// 2x multilinear upsampling per spatial axis with edge clamp.
//
// FINAL (R7 = R1 + micro-cleanup). One thread per (input voxel, channel
// quad): load the 2x2x2 clamped corner neighborhood (8 x float4), write the
// 8 generated output voxels with streaming stores. Weights are exact powers
// of two; edge clamp reproduces the reference's mid = 0.5*(v+v) = v at the
// last index.
//
// Measured conclusion after 6 profiled variants: steady-state DRAM traffic
// is exactly the 440 MB output (input stays L2-resident across graph
// replays thanks to the .cs streaming stores), pinned at ~5.95 TB/s — the
// chip's pure-write ceiling. Store width/path/density, wave shape, and
// occupancy are all non-factors; this configuration is the floor.

#define DD 80
#define HH 96
#define WW 112
// C = 16 floats = 4 float4 quads per voxel

__device__ __forceinline__ float4 f4_avg2(float4 a, float4 b) {
    return make_float4(0.5f * (a.x + b.x), 0.5f * (a.y + b.y),
                       0.5f * (a.z + b.z), 0.5f * (a.w + b.w));
}
__device__ __forceinline__ float4 f4_avg4(float4 a, float4 b, float4 c, float4 d) {
    return make_float4(0.25f * (a.x + b.x + c.x + d.x),
                       0.25f * (a.y + b.y + c.y + d.y),
                       0.25f * (a.z + b.z + c.z + d.z),
                       0.25f * (a.w + b.w + c.w + d.w));
}
__device__ __forceinline__ float4 f4_avg8(float4 a, float4 b, float4 c, float4 d,
                                          float4 e, float4 f, float4 g, float4 h) {
    return make_float4(0.125f * (a.x + b.x + c.x + d.x + e.x + f.x + g.x + h.x),
                       0.125f * (a.y + b.y + c.y + d.y + e.y + f.y + g.y + h.y),
                       0.125f * (a.z + b.z + c.z + d.z + e.z + f.z + g.z + h.z),
                       0.125f * (a.w + b.w + c.w + d.w + e.w + f.w + g.w + h.w));
}

__global__ void __launch_bounds__(256)
upsample_2x_kernel(const float4* __restrict__ in, float4* __restrict__ out) {
    const int tid = blockIdx.x * 256 + threadIdx.x;

    // block is a multiple of 4, so tid&3 == threadIdx.x&3 (uniform-friendly)
    const int c4 = threadIdx.x & 3;
    const int t  = tid >> 2;
    const int x  = t % WW;
    const int t2 = t / WW;
    const int y  = t2 % HH;
    const int z  = t2 / HH;

    const int xp = min(x + 1, WW - 1);
    const int yp = min(y + 1, HH - 1);
    const int zp = min(z + 1, DD - 1);

    // input float4 index
    #define IIDX(zz, yy, xx) ((((zz) * HH + (yy)) * WW + (xx)) * 4 + c4)
    float4 v000 = in[IIDX(z,  y,  x )];
    float4 v001 = in[IIDX(z,  y,  xp)];
    float4 v010 = in[IIDX(z,  yp, x )];
    float4 v011 = in[IIDX(z,  yp, xp)];
    float4 v100 = in[IIDX(zp, y,  x )];
    float4 v101 = in[IIDX(zp, y,  xp)];
    float4 v110 = in[IIDX(zp, yp, x )];
    float4 v111 = in[IIDX(zp, yp, xp)];
    #undef IIDX

    const int zo = 2 * z, yo = 2 * y, xo = 2 * x;
    // output float4 index (dims 2*DD x 2*HH x 2*WW)
    #define OIDX(zz, yy, xx) ((((zz) * (2 * HH) + (yy)) * (2 * WW) + (xx)) * 4 + c4)

    __stcs(&out[OIDX(zo,     yo,     xo    )], v000);
    __stcs(&out[OIDX(zo,     yo,     xo + 1)], f4_avg2(v000, v001));
    __stcs(&out[OIDX(zo,     yo + 1, xo    )], f4_avg2(v000, v010));
    __stcs(&out[OIDX(zo,     yo + 1, xo + 1)], f4_avg4(v000, v001, v010, v011));
    __stcs(&out[OIDX(zo + 1, yo,     xo    )], f4_avg2(v000, v100));
    __stcs(&out[OIDX(zo + 1, yo,     xo + 1)], f4_avg4(v000, v001, v100, v101));
    __stcs(&out[OIDX(zo + 1, yo + 1, xo    )], f4_avg4(v000, v010, v100, v110));
    __stcs(&out[OIDX(zo + 1, yo + 1, xo + 1)], f4_avg8(v000, v001, v010, v011,
                                                       v100, v101, v110, v111));
    #undef OIDX
}

extern "C" void kernel_launch(void* const* d_in, const int* in_sizes, int n_in,
                              void* d_out, int out_size) {
    const float4* in  = (const float4*)d_in[0];
    float4*       out = (float4*)d_out;

    const int total_threads = DD * HH * WW * 4;  // 3,440,640
    const int block = 256;
    const int grid  = total_threads / block;     // 13,440 exactly

    upsample_2x_kernel<<<grid, block>>>(in, out);
}